// round 14
// baseline (speedup 1.0000x reference)
#include <cuda_runtime.h>
#include <cuda_fp16.h>
#include <math.h>

#define FIN   256
#define HC1   128
#define H1    4
#define C1    32
#define C2    16
#define MAXN  50016
#define MAXTOT 861000
#define EPSV  1e-16f
#define FULLM 0xffffffffu

// ---------------- device scratch --------------------------------------------
__device__ int   g_deg[MAXN];
__device__ int   g_rowptr[MAXN + 1];
__device__ int   g_pos[MAXTOT];
__device__ int   g_csr[MAXTOT];
__device__ __half g_h1[MAXN * HC1];
__device__ float g_as1[MAXN * H1];
__device__ float g_ad1[MAXN * H1];
__device__ __half g_h2[MAXN * C2];
__device__ float g_as2[MAXN];
__device__ float g_ad2[MAXN];

__device__ __forceinline__ float lrelu(float x) { return x > 0.f ? x : 0.2f * x; }

__device__ __forceinline__ unsigned f2tf32(float f) {
    unsigned r;
    asm("cvt.rna.tf32.f32 %0, %1;" : "=r"(r) : "f"(f));
    return r;
}

__device__ __forceinline__ void mma_tf32(float c[4], const unsigned a[4], const unsigned b[2]) {
    asm volatile("mma.sync.aligned.m16n8k8.row.col.f32.tf32.tf32.f32 "
        "{%0,%1,%2,%3}, {%4,%5,%6,%7}, {%8,%9}, {%0,%1,%2,%3};"
        : "+f"(c[0]), "+f"(c[1]), "+f"(c[2]), "+f"(c[3])
        : "r"(a[0]), "r"(a[1]), "r"(a[2]), "r"(a[3]), "r"(b[0]), "r"(b[1]));
}

// ---------------- CSR build ---------------------------------------------------
// deg starts at 0 (memset node); self-loop accounted as +1 inside the scan.
__global__ void k_histp(const int* __restrict__ dst, int E) {
    int t4 = (blockIdx.x * blockDim.x + threadIdx.x) * 4;
    if (t4 + 3 < E) {
        int4 d = *reinterpret_cast<const int4*>(&dst[t4]);
        int4 p;
        p.x = atomicAdd(&g_deg[d.x], 1);
        p.y = atomicAdd(&g_deg[d.y], 1);
        p.z = atomicAdd(&g_deg[d.z], 1);
        p.w = atomicAdd(&g_deg[d.w], 1);
        *reinterpret_cast<int4*>(&g_pos[t4]) = p;
    } else {
        for (int i = t4; i < E; i++) g_pos[i] = atomicAdd(&g_deg[dst[i]], 1);
    }
}

// single-block fused scan: rowptr (exclusive, with +1 self-loop per node),
// writes self-loops into slot 0, writes rowptr[N].
__global__ void k_scanone(int N) {
    __shared__ int wsum[32];
    const int tid = threadIdx.x;
    const int lane = tid & 31, w = tid >> 5;
    const int chunk = (N + 1023) >> 10;
    const int start = tid * chunk;

    int s = 0;
    for (int i = 0; i < chunk; i++) {
        int idx = start + i;
        if (idx < N) s += g_deg[idx] + 1;
    }
    // block-wide exclusive scan of per-thread sums
    int x = s;
#pragma unroll
    for (int o = 1; o < 32; o <<= 1) {
        int y = __shfl_up_sync(FULLM, x, o);
        if (lane >= o) x += y;
    }
    if (lane == 31) wsum[w] = x;
    __syncthreads();
    if (w == 0) {
        int v = (lane < 32) ? wsum[lane] : 0;
#pragma unroll
        for (int o = 1; o < 32; o <<= 1) {
            int y = __shfl_up_sync(FULLM, v, o);
            if (lane >= o) v += y;
        }
        wsum[lane] = v;
    }
    __syncthreads();
    int run = x - s + ((w > 0) ? wsum[w - 1] : 0);   // exclusive prefix for this thread
    for (int i = 0; i < chunk; i++) {
        int idx = start + i;
        if (idx < N) {
            g_rowptr[idx] = run;
            g_csr[run] = idx;             // self-loop in slot 0
            run += g_deg[idx] + 1;
        }
    }
    if (tid == 1023) g_rowptr[N] = wsum[31];
}

// atomic-free scatter using recorded positions (slot 0 = self-loop -> +1)
__global__ void k_scatter2(const int* __restrict__ src, const int* __restrict__ dst, int E) {
    int t4 = (blockIdx.x * blockDim.x + threadIdx.x) * 4;
    if (t4 + 3 < E) {
        int4 s = *reinterpret_cast<const int4*>(&src[t4]);
        int4 d = *reinterpret_cast<const int4*>(&dst[t4]);
        int4 p = *reinterpret_cast<const int4*>(&g_pos[t4]);
        g_csr[g_rowptr[d.x] + 1 + p.x] = s.x;
        g_csr[g_rowptr[d.y] + 1 + p.y] = s.y;
        g_csr[g_rowptr[d.z] + 1 + p.z] = s.z;
        g_csr[g_rowptr[d.w] + 1 + p.w] = s.w;
    } else {
        for (int i = t4; i < E; i++)
            g_csr[g_rowptr[dst[i]] + 1 + g_pos[i]] = src[i];
    }
}

// ---------------- GEMM1: tf32 TC, BM=64, cp.async double buffer --------------
#define BK 16

__global__ void __launch_bounds__(256, 3)
k_gemm1_tc(const float* __restrict__ A, const float* __restrict__ B,
           const float* __restrict__ a_s, const float* __restrict__ a_d, int M) {
    __shared__ float As[2][64][20];
    __shared__ float Bs[2][16][136];

    const int tid = threadIdx.x;
    const int wid = tid >> 5, lane = tid & 31;
    const int wm = wid >> 2;
    const int wn = wid & 3;
    const int block_row = blockIdx.x * 64;
    const int g = lane >> 2, t = lane & 3;

    float acc[2][4][4];
#pragma unroll
    for (int i = 0; i < 2; i++)
#pragma unroll
        for (int j = 0; j < 4; j++)
#pragma unroll
            for (int q = 0; q < 4; q++) acc[i][j][q] = 0.f;

    const int arow = tid >> 2;
    const int akc  = (tid & 3) * 4;
    const int brow = tid >> 5;
    const int bcol = (tid & 31) * 4;

    const int ar = block_row + arow;
    const float* a_src = &A[(size_t)(ar < M ? ar : (M - 1)) * FIN + akc];
    const int a_sz = (ar < M) ? 16 : 0;

#define LOAD_TILE(k0, buf)                                                              \
    {                                                                                   \
        unsigned d0 = (unsigned)__cvta_generic_to_shared(&As[buf][arow][akc]);          \
        asm volatile("cp.async.ca.shared.global [%0], [%1], 16, %2;"                    \
                     :: "r"(d0), "l"(a_src + (k0)), "r"(a_sz));                         \
        unsigned d1 = (unsigned)__cvta_generic_to_shared(&Bs[buf][brow][bcol]);         \
        asm volatile("cp.async.ca.shared.global [%0], [%1], 16;"                        \
                     :: "r"(d1), "l"(&B[((k0) + brow) * HC1 + bcol]));                  \
        unsigned d2 = (unsigned)__cvta_generic_to_shared(&Bs[buf][brow + 8][bcol]);     \
        asm volatile("cp.async.ca.shared.global [%0], [%1], 16;"                        \
                     :: "r"(d2), "l"(&B[((k0) + brow + 8) * HC1 + bcol]));              \
    }

    LOAD_TILE(0, 0);
    asm volatile("cp.async.commit_group;");

#pragma unroll 1
    for (int s = 0; s < FIN / BK; s++) {
        const int buf = s & 1;
        if (s < FIN / BK - 1) {
            LOAD_TILE((s + 1) * BK, buf ^ 1);
            asm volatile("cp.async.commit_group;");
            asm volatile("cp.async.wait_group 1;");
        } else {
            asm volatile("cp.async.wait_group 0;");
        }
        __syncthreads();

#pragma unroll
        for (int kk = 0; kk < BK; kk += 8) {
            unsigned bh[4][2];
#pragma unroll
            for (int n = 0; n < 4; n++) {
                int n0 = wn * 32 + n * 8;
                bh[n][0] = f2tf32(Bs[buf][kk + t][n0 + g]);
                bh[n][1] = f2tf32(Bs[buf][kk + t + 4][n0 + g]);
            }
#pragma unroll
            for (int m = 0; m < 2; m++) {
                int m0 = wm * 32 + m * 16;
                float a0 = As[buf][m0 + g][kk + t];
                float a1 = As[buf][m0 + g + 8][kk + t];
                float a2 = As[buf][m0 + g][kk + t + 4];
                float a3 = As[buf][m0 + g + 8][kk + t + 4];
                unsigned ah[4], al[4];
                ah[0] = f2tf32(a0); al[0] = f2tf32(a0 - __uint_as_float(ah[0]));
                ah[1] = f2tf32(a1); al[1] = f2tf32(a1 - __uint_as_float(ah[1]));
                ah[2] = f2tf32(a2); al[2] = f2tf32(a2 - __uint_as_float(ah[2]));
                ah[3] = f2tf32(a3); al[3] = f2tf32(a3 - __uint_as_float(ah[3]));
#pragma unroll
                for (int n = 0; n < 4; n++) {
                    mma_tf32(acc[m][n], ah, bh[n]);
                    mma_tf32(acc[m][n], al, bh[n]);
                }
            }
        }
        __syncthreads();
    }

    float cs[8], cd[8];
#pragma unroll
    for (int n = 0; n < 4; n++) {
        int c = wn * 32 + n * 8 + 2 * t;
        cs[n * 2]     = __ldg(&a_s[c]);
        cs[n * 2 + 1] = __ldg(&a_s[c + 1]);
        cd[n * 2]     = __ldg(&a_d[c]);
        cd[n * 2 + 1] = __ldg(&a_d[c + 1]);
    }

#pragma unroll
    for (int m = 0; m < 2; m++) {
        int row0 = block_row + wm * 32 + m * 16 + g;
        int row1 = row0 + 8;
        float s0 = 0.f, s1 = 0.f, d0 = 0.f, d1 = 0.f;
#pragma unroll
        for (int n = 0; n < 4; n++) {
            int col = wn * 32 + n * 8 + 2 * t;
            if (row0 < M)
                *reinterpret_cast<__half2*>(&g_h1[(long)row0 * HC1 + col]) =
                    __floats2half2_rn(acc[m][n][0], acc[m][n][1]);
            if (row1 < M)
                *reinterpret_cast<__half2*>(&g_h1[(long)row1 * HC1 + col]) =
                    __floats2half2_rn(acc[m][n][2], acc[m][n][3]);
            s0 = fmaf(acc[m][n][0], cs[n * 2], fmaf(acc[m][n][1], cs[n * 2 + 1], s0));
            s1 = fmaf(acc[m][n][2], cs[n * 2], fmaf(acc[m][n][3], cs[n * 2 + 1], s1));
            d0 = fmaf(acc[m][n][0], cd[n * 2], fmaf(acc[m][n][1], cd[n * 2 + 1], d0));
            d1 = fmaf(acc[m][n][2], cd[n * 2], fmaf(acc[m][n][3], cd[n * 2 + 1], d1));
        }
#pragma unroll
        for (int o = 1; o <= 2; o <<= 1) {
            s0 += __shfl_xor_sync(FULLM, s0, o);
            s1 += __shfl_xor_sync(FULLM, s1, o);
            d0 += __shfl_xor_sync(FULLM, d0, o);
            d1 += __shfl_xor_sync(FULLM, d1, o);
        }
        if (t == 0) {
            if (row0 < M) { g_as1[row0 * H1 + wn] = s0; g_ad1[row0 * H1 + wn] = d0; }
            if (row1 < M) { g_as1[row1 * H1 + wn] = s1; g_ad1[row1 * H1 + wn] = d1; }
        }
    }
}

// ---------------- fused attn1 + ELU + gemm2 + layer-2 logits -----------------
__global__ void __launch_bounds__(256)
k_attn1f(const float* __restrict__ b1, const float* __restrict__ W2,
         const float* __restrict__ a_s2, const float* __restrict__ a_d2, int N) {
    __shared__ float w2s[HC1 * C2];
    __shared__ float hs[8][HC1 + 4];
    __shared__ int   s_src[8][32];
    __shared__ float s_w[8][32][4];

    const int tid = threadIdx.x;
    const int wid = tid >> 5, lane = tid & 31;
#pragma unroll
    for (int i = tid; i < HC1 * C2; i += 256) w2s[i] = W2[i];
    __syncthreads();

    const int node = blockIdx.x * 8 + wid;
    if (node < N) {
        const int beg = g_rowptr[node], end = g_rowptr[node + 1];
        const float4 ad4 = *reinterpret_cast<const float4*>(&g_ad1[node * H1]);
        const int half = lane >> 4;
        const int hc   = lane & 15;
        const int headp = hc >> 2;

        float acc8[8];
#pragma unroll
        for (int i = 0; i < 8; i++) acc8[i] = 0.f;
        float4 ssum = make_float4(0.f, 0.f, 0.f, 0.f);

        for (int base = beg; base < end; base += 32) {
            int i = base + lane;
            int src_l = 0;
            float4 w4 = make_float4(0.f, 0.f, 0.f, 0.f);
            if (i < end) {
                src_l = g_csr[i];
                float4 as4 = *reinterpret_cast<const float4*>(&g_as1[src_l * H1]);
                w4.x = __expf(lrelu(as4.x + ad4.x));
                w4.y = __expf(lrelu(as4.y + ad4.y));
                w4.z = __expf(lrelu(as4.z + ad4.z));
                w4.w = __expf(lrelu(as4.w + ad4.w));
            }
            ssum.x += w4.x; ssum.y += w4.y; ssum.z += w4.z; ssum.w += w4.w;
            s_src[wid][lane] = src_l;
            *reinterpret_cast<float4*>(&s_w[wid][lane][0]) = w4;
            __syncwarp();

            int cnt = min(32, end - base);
            for (int j = 0; j < cnt; j += 8) {
                int p[4]; float wg[4];
#pragma unroll
                for (int q = 0; q < 4; q++) {
                    int e = j + q * 2 + half;
                    p[q]  = s_src[wid][e];
                    wg[q] = s_w[wid][e][headp];
                }
                uint4 v[4];
#pragma unroll
                for (int q = 0; q < 4; q++)
                    v[q] = *reinterpret_cast<const uint4*>(&g_h1[(long)p[q] * HC1 + hc * 8]);
#pragma unroll
                for (int q = 0; q < 4; q++) {
                    float2 f0 = __half22float2(*reinterpret_cast<__half2*>(&v[q].x));
                    float2 f1 = __half22float2(*reinterpret_cast<__half2*>(&v[q].y));
                    float2 f2 = __half22float2(*reinterpret_cast<__half2*>(&v[q].z));
                    float2 f3 = __half22float2(*reinterpret_cast<__half2*>(&v[q].w));
                    acc8[0] = fmaf(f0.x, wg[q], acc8[0]);
                    acc8[1] = fmaf(f0.y, wg[q], acc8[1]);
                    acc8[2] = fmaf(f1.x, wg[q], acc8[2]);
                    acc8[3] = fmaf(f1.y, wg[q], acc8[3]);
                    acc8[4] = fmaf(f2.x, wg[q], acc8[4]);
                    acc8[5] = fmaf(f2.y, wg[q], acc8[5]);
                    acc8[6] = fmaf(f3.x, wg[q], acc8[6]);
                    acc8[7] = fmaf(f3.y, wg[q], acc8[7]);
                }
            }
            __syncwarp();
        }
#pragma unroll
        for (int i = 0; i < 8; i++) acc8[i] += __shfl_xor_sync(FULLM, acc8[i], 16);
#pragma unroll
        for (int o = 16; o; o >>= 1) {
            ssum.x += __shfl_xor_sync(FULLM, ssum.x, o);
            ssum.y += __shfl_xor_sync(FULLM, ssum.y, o);
            ssum.z += __shfl_xor_sync(FULLM, ssum.z, o);
            ssum.w += __shfl_xor_sync(FULLM, ssum.w, o);
        }
        if (lane < 16) {
            float sh = (headp < 2) ? (headp == 0 ? ssum.x : ssum.y)
                                   : (headp == 2 ? ssum.z : ssum.w);
            float inv = 1.f / (sh + EPSV);
            float4 bb0 = *reinterpret_cast<const float4*>(&b1[hc * 8]);
            float4 bb1 = *reinterpret_cast<const float4*>(&b1[hc * 8 + 4]);
            float o8[8];
            o8[0] = fmaf(acc8[0], inv, bb0.x);
            o8[1] = fmaf(acc8[1], inv, bb0.y);
            o8[2] = fmaf(acc8[2], inv, bb0.z);
            o8[3] = fmaf(acc8[3], inv, bb0.w);
            o8[4] = fmaf(acc8[4], inv, bb1.x);
            o8[5] = fmaf(acc8[5], inv, bb1.y);
            o8[6] = fmaf(acc8[6], inv, bb1.z);
            o8[7] = fmaf(acc8[7], inv, bb1.w);
#pragma unroll
            for (int i = 0; i < 8; i++)
                o8[i] = o8[i] > 0.f ? o8[i] : (__expf(o8[i]) - 1.f);
            *reinterpret_cast<float4*>(&hs[wid][hc * 8])     = *reinterpret_cast<float4*>(&o8[0]);
            *reinterpret_cast<float4*>(&hs[wid][hc * 8 + 4]) = *reinterpret_cast<float4*>(&o8[4]);
        }
    }
    __syncwarp();

    if (node < N) {
        const int c = lane & 15, sub = lane >> 4;
        float acc2 = 0.f;
#pragma unroll
        for (int kk = 0; kk < 16; kk++) {
            int k = sub * 64 + kk * 4;
            float4 hv = *reinterpret_cast<const float4*>(&hs[wid][k]);
            acc2 = fmaf(hv.x, w2s[(k + 0) * C2 + c], acc2);
            acc2 = fmaf(hv.y, w2s[(k + 1) * C2 + c], acc2);
            acc2 = fmaf(hv.z, w2s[(k + 2) * C2 + c], acc2);
            acc2 = fmaf(hv.w, w2s[(k + 3) * C2 + c], acc2);
        }
        acc2 += __shfl_xor_sync(FULLM, acc2, 16);

        float s = acc2 * __ldg(&a_s2[c]);
        float d = acc2 * __ldg(&a_d2[c]);
#pragma unroll
        for (int o = 8; o; o >>= 1) {
            s += __shfl_xor_sync(FULLM, s, o);
            d += __shfl_xor_sync(FULLM, d, o);
        }
        if (lane < 16) {
            g_h2[node * C2 + c] = __float2half_rn(acc2);
            if (c == 0) { g_as2[node] = s; g_ad2[node] = d; }
        }
    }
}

// ---------------- attention + aggregate, layer 2 (fp16 h2) -------------------
__global__ void __launch_bounds__(256)
k_attn2(const float* __restrict__ b2, float* __restrict__ out, int N) {
    __shared__ int   s_src[8][32];
    __shared__ float s_w[8][32];

    int tid = threadIdx.x;
    int wid = tid >> 5, lane = tid & 31;
    int w = blockIdx.x * 8 + wid;
    if (w >= N) return;
    int beg = g_rowptr[w], end = g_rowptr[w + 1];
    float adv = g_ad2[w];
    int cc = lane & 15;
    int half = (lane >> 4) * 16;

    float acc = 0.f, ssum = 0.f;
    for (int base = beg; base < end; base += 32) {
        int i = base + lane;
        int src_l = 0; float wt_l = 0.f;
        if (i < end) {
            src_l = g_csr[i];
            wt_l = __expf(lrelu(g_as2[src_l] + adv));
        }
        ssum += wt_l;
        s_src[wid][lane] = src_l;
        s_w[wid][lane] = wt_l;
        __syncwarp();
#pragma unroll
        for (int jj = 0; jj < 16; jj += 8) {
            int p[8]; float wg[8];
#pragma unroll
            for (int q = 0; q < 8; q++) {
                p[q]  = s_src[wid][half + jj + q];
                wg[q] = s_w[wid][half + jj + q];
            }
            float vv[8];
#pragma unroll
            for (int q = 0; q < 8; q++) vv[q] = __half2float(g_h2[p[q] * C2 + cc]);
#pragma unroll
            for (int q = 0; q < 8; q++) acc = fmaf(vv[q], wg[q], acc);
        }
        __syncwarp();
    }
    acc += __shfl_xor_sync(FULLM, acc, 16);
#pragma unroll
    for (int o = 16; o; o >>= 1) ssum += __shfl_xor_sync(FULLM, ssum, o);
    if (lane < 16) out[w * C2 + lane] = acc / (ssum + EPSV) + b2[lane];
}

// ---------------- launch -----------------------------------------------------
extern "C" void kernel_launch(void* const* d_in, const int* in_sizes, int n_in,
                              void* d_out, int out_size) {
    const float* x    = (const float*)d_in[0];
    const int*   ei   = (const int*)d_in[1];
    const float* W1   = (const float*)d_in[2];
    const float* a_s1 = (const float*)d_in[3];
    const float* a_d1 = (const float*)d_in[4];
    const float* b1   = (const float*)d_in[5];
    const float* W2   = (const float*)d_in[6];
    const float* a_s2 = (const float*)d_in[7];
    const float* a_d2 = (const float*)d_in[8];
    const float* b2   = (const float*)d_in[9];
    float* out = (float*)d_out;

    const int Fin = in_sizes[2] / in_sizes[5];   // 256
    const int N   = in_sizes[0] / Fin;           // 50000
    const int E   = in_sizes[1] / 2;             // 800000

    static cudaStream_t s2 = nullptr;
    static cudaEvent_t  evA = nullptr, evB = nullptr;
    static int* deg_ptr = nullptr;
    if (s2 == nullptr) {
        cudaStreamCreateWithFlags(&s2, cudaStreamNonBlocking);
        cudaEventCreateWithFlags(&evA, cudaEventDisableTiming);
        cudaEventCreateWithFlags(&evB, cudaEventDisableTiming);
        cudaGetSymbolAddress((void**)&deg_ptr, g_deg);
    }

    // fork: CSR build on s2, GEMM1 on main stream
    cudaEventRecord(evA, 0);
    cudaStreamWaitEvent(s2, evA, 0);

    k_gemm1_tc<<<(N + 63) / 64, 256>>>(x, W1, a_s1, a_d1, N);

    cudaMemsetAsync(deg_ptr, 0, N * sizeof(int), s2);
    k_histp<<<(E / 4 + 256) / 256, 256, 0, s2>>>(ei + E, E);
    k_scanone<<<1, 1024, 0, s2>>>(N);
    k_scatter2<<<(E / 4 + 256) / 256, 256, 0, s2>>>(ei, ei + E, E);

    // join
    cudaEventRecord(evB, s2);
    cudaStreamWaitEvent(0, evB, 0);

    // fused layer-1 aggregate + ELU + gemm2 + layer-2 logits
    k_attn1f<<<(N + 7) / 8, 256>>>(b1, W2, a_s2, a_d2, N);

    // layer-2 aggregate
    k_attn2<<<(N + 7) / 8, 256>>>(b2, out, N);
}

// round 15
// speedup vs baseline: 1.7382x; 1.7382x over previous
#include <cuda_runtime.h>
#include <cuda_fp16.h>
#include <math.h>

#define FIN   256
#define HC1   128
#define H1    4
#define C1    32
#define C2    16
#define MAXN  50016
#define MAXTOT 861000
#define EPSV  1e-16f
#define FULLM 0xffffffffu

// ---------------- device scratch --------------------------------------------
__device__ int   g_deg[MAXN];
__device__ int   g_rowptr[MAXN + 1];
__device__ int   g_part[256];
__device__ int   g_pos[MAXTOT];
__device__ int   g_csr[MAXTOT];
__device__ __half g_h1[MAXN * HC1];
__device__ float g_as1[MAXN * H1];
__device__ float g_ad1[MAXN * H1];
__device__ __half g_h2[MAXN * C2];
__device__ float g_as2[MAXN];
__device__ float g_ad2[MAXN];

__device__ __forceinline__ float lrelu(float x) { return x > 0.f ? x : 0.2f * x; }

__device__ __forceinline__ unsigned f2tf32(float f) {
    unsigned r;
    asm("cvt.rna.tf32.f32 %0, %1;" : "=r"(r) : "f"(f));
    return r;
}

__device__ __forceinline__ void mma_tf32(float c[4], const unsigned a[4], const unsigned b[2]) {
    asm volatile("mma.sync.aligned.m16n8k8.row.col.f32.tf32.tf32.f32 "
        "{%0,%1,%2,%3}, {%4,%5,%6,%7}, {%8,%9}, {%0,%1,%2,%3};"
        : "+f"(c[0]), "+f"(c[1]), "+f"(c[2]), "+f"(c[3])
        : "r"(a[0]), "r"(a[1]), "r"(a[2]), "r"(a[3]), "r"(b[0]), "r"(b[1]));
}

// ---------------- CSR build (R13 multi-block form) ----------------------------
__global__ void k_zero(int N) {
    int t = blockIdx.x * blockDim.x + threadIdx.x;
    if (t < N) g_deg[t] = 1;            // slot 0 reserved for self-loop
}

__global__ void k_histp(const int* __restrict__ dst, int E) {
    int t4 = (blockIdx.x * blockDim.x + threadIdx.x) * 4;
    if (t4 + 3 < E) {
        int4 d = *reinterpret_cast<const int4*>(&dst[t4]);
        int4 p;
        p.x = atomicAdd(&g_deg[d.x], 1);
        p.y = atomicAdd(&g_deg[d.y], 1);
        p.z = atomicAdd(&g_deg[d.z], 1);
        p.w = atomicAdd(&g_deg[d.w], 1);
        *reinterpret_cast<int4*>(&g_pos[t4]) = p;
    } else {
        for (int i = t4; i < E; i++) g_pos[i] = atomicAdd(&g_deg[dst[i]], 1);
    }
}

__global__ void k_scan1(int N) {
    int tid = threadIdx.x, b = blockIdx.x;
    int i = b * 256 + tid;
    int v = (i < N) ? g_deg[i] : 0;
    int lane = tid & 31, w = tid >> 5;
    int x = v;
#pragma unroll
    for (int o = 1; o < 32; o <<= 1) {
        int y = __shfl_up_sync(FULLM, x, o);
        if (lane >= o) x += y;
    }
    __shared__ int ws[8];
    if (lane == 31) ws[w] = x;
    __syncthreads();
    if (w == 0) {
        int s = (lane < 8) ? ws[lane] : 0;
#pragma unroll
        for (int o = 1; o < 8; o <<= 1) {
            int y = __shfl_up_sync(FULLM, s, o);
            if (lane >= o) s += y;
        }
        if (lane < 8) ws[lane] = s;
    }
    __syncthreads();
    int incl = x + ((w > 0) ? ws[w - 1] : 0);
    if (i < N) g_rowptr[i] = incl - v;
    if (tid == 255) g_part[b] = incl;
}

__global__ void k_scan2(int P, int N) {
    int tid = threadIdx.x;
    int v = (tid < P) ? g_part[tid] : 0;
    int lane = tid & 31, w = tid >> 5;
    int x = v;
#pragma unroll
    for (int o = 1; o < 32; o <<= 1) {
        int y = __shfl_up_sync(FULLM, x, o);
        if (lane >= o) x += y;
    }
    __shared__ int ws[8];
    if (lane == 31) ws[w] = x;
    __syncthreads();
    if (w == 0) {
        int s = (lane < 8) ? ws[lane] : 0;
#pragma unroll
        for (int o = 1; o < 8; o <<= 1) {
            int y = __shfl_up_sync(FULLM, s, o);
            if (lane >= o) s += y;
        }
        if (lane < 8) ws[lane] = s;
    }
    __syncthreads();
    int incl = x + ((w > 0) ? ws[w - 1] : 0);
    if (tid < P) g_part[tid] = incl - v;
    if (tid == 255) g_rowptr[N] = incl;
}

// finalize rowptr + write self-loop into slot 0
__global__ void k_scan3(int N) {
    int i = blockIdx.x * blockDim.x + threadIdx.x;
    if (i < N) {
        int r = g_rowptr[i] + g_part[i >> 8];
        g_rowptr[i] = r;
        g_csr[r] = i;
    }
}

// atomic-free scatter using recorded positions (pos starts at 1: self-loop slot 0)
__global__ void k_scatter2(const int* __restrict__ src, const int* __restrict__ dst, int E) {
    int t4 = (blockIdx.x * blockDim.x + threadIdx.x) * 4;
    if (t4 + 3 < E) {
        int4 s = *reinterpret_cast<const int4*>(&src[t4]);
        int4 d = *reinterpret_cast<const int4*>(&dst[t4]);
        int4 p = *reinterpret_cast<const int4*>(&g_pos[t4]);
        g_csr[g_rowptr[d.x] + p.x] = s.x;
        g_csr[g_rowptr[d.y] + p.y] = s.y;
        g_csr[g_rowptr[d.z] + p.z] = s.z;
        g_csr[g_rowptr[d.w] + p.w] = s.w;
    } else {
        for (int i = t4; i < E; i++)
            g_csr[g_rowptr[dst[i]] + g_pos[i]] = src[i];
    }
}

// ---------------- GEMM1: 1-pass tf32 TC, BM=64, cp.async double buffer -------
#define BK 16

__global__ void __launch_bounds__(256, 3)
k_gemm1_tc(const float* __restrict__ A, const float* __restrict__ B,
           const float* __restrict__ a_s, const float* __restrict__ a_d, int M) {
    __shared__ float As[2][64][20];
    __shared__ float Bs[2][16][136];

    const int tid = threadIdx.x;
    const int wid = tid >> 5, lane = tid & 31;
    const int wm = wid >> 2;
    const int wn = wid & 3;
    const int block_row = blockIdx.x * 64;
    const int g = lane >> 2, t = lane & 3;

    float acc[2][4][4];
#pragma unroll
    for (int i = 0; i < 2; i++)
#pragma unroll
        for (int j = 0; j < 4; j++)
#pragma unroll
            for (int q = 0; q < 4; q++) acc[i][j][q] = 0.f;

    const int arow = tid >> 2;
    const int akc  = (tid & 3) * 4;
    const int brow = tid >> 5;
    const int bcol = (tid & 31) * 4;

    const int ar = block_row + arow;
    const float* a_src = &A[(size_t)(ar < M ? ar : (M - 1)) * FIN + akc];
    const int a_sz = (ar < M) ? 16 : 0;

#define LOAD_TILE(k0, buf)                                                              \
    {                                                                                   \
        unsigned d0 = (unsigned)__cvta_generic_to_shared(&As[buf][arow][akc]);          \
        asm volatile("cp.async.ca.shared.global [%0], [%1], 16, %2;"                    \
                     :: "r"(d0), "l"(a_src + (k0)), "r"(a_sz));                         \
        unsigned d1 = (unsigned)__cvta_generic_to_shared(&Bs[buf][brow][bcol]);         \
        asm volatile("cp.async.ca.shared.global [%0], [%1], 16;"                        \
                     :: "r"(d1), "l"(&B[((k0) + brow) * HC1 + bcol]));                  \
        unsigned d2 = (unsigned)__cvta_generic_to_shared(&Bs[buf][brow + 8][bcol]);     \
        asm volatile("cp.async.ca.shared.global [%0], [%1], 16;"                        \
                     :: "r"(d2), "l"(&B[((k0) + brow + 8) * HC1 + bcol]));              \
    }

    LOAD_TILE(0, 0);
    asm volatile("cp.async.commit_group;");

#pragma unroll 1
    for (int s = 0; s < FIN / BK; s++) {
        const int buf = s & 1;
        if (s < FIN / BK - 1) {
            LOAD_TILE((s + 1) * BK, buf ^ 1);
            asm volatile("cp.async.commit_group;");
            asm volatile("cp.async.wait_group 1;");
        } else {
            asm volatile("cp.async.wait_group 0;");
        }
        __syncthreads();

#pragma unroll
        for (int kk = 0; kk < BK; kk += 8) {
            unsigned bh[4][2];
#pragma unroll
            for (int n = 0; n < 4; n++) {
                int n0 = wn * 32 + n * 8;
                bh[n][0] = f2tf32(Bs[buf][kk + t][n0 + g]);
                bh[n][1] = f2tf32(Bs[buf][kk + t + 4][n0 + g]);
            }
#pragma unroll
            for (int m = 0; m < 2; m++) {
                int m0 = wm * 32 + m * 16;
                unsigned ah[4];
                ah[0] = f2tf32(As[buf][m0 + g][kk + t]);
                ah[1] = f2tf32(As[buf][m0 + g + 8][kk + t]);
                ah[2] = f2tf32(As[buf][m0 + g][kk + t + 4]);
                ah[3] = f2tf32(As[buf][m0 + g + 8][kk + t + 4]);
#pragma unroll
                for (int n = 0; n < 4; n++) {
                    mma_tf32(acc[m][n], ah, bh[n]);
                }
            }
        }
        __syncthreads();
    }

    float cs[8], cd[8];
#pragma unroll
    for (int n = 0; n < 4; n++) {
        int c = wn * 32 + n * 8 + 2 * t;
        cs[n * 2]     = __ldg(&a_s[c]);
        cs[n * 2 + 1] = __ldg(&a_s[c + 1]);
        cd[n * 2]     = __ldg(&a_d[c]);
        cd[n * 2 + 1] = __ldg(&a_d[c + 1]);
    }

#pragma unroll
    for (int m = 0; m < 2; m++) {
        int row0 = block_row + wm * 32 + m * 16 + g;
        int row1 = row0 + 8;
        float s0 = 0.f, s1 = 0.f, d0 = 0.f, d1 = 0.f;
#pragma unroll
        for (int n = 0; n < 4; n++) {
            int col = wn * 32 + n * 8 + 2 * t;
            if (row0 < M)
                *reinterpret_cast<__half2*>(&g_h1[(long)row0 * HC1 + col]) =
                    __floats2half2_rn(acc[m][n][0], acc[m][n][1]);
            if (row1 < M)
                *reinterpret_cast<__half2*>(&g_h1[(long)row1 * HC1 + col]) =
                    __floats2half2_rn(acc[m][n][2], acc[m][n][3]);
            s0 = fmaf(acc[m][n][0], cs[n * 2], fmaf(acc[m][n][1], cs[n * 2 + 1], s0));
            s1 = fmaf(acc[m][n][2], cs[n * 2], fmaf(acc[m][n][3], cs[n * 2 + 1], s1));
            d0 = fmaf(acc[m][n][0], cd[n * 2], fmaf(acc[m][n][1], cd[n * 2 + 1], d0));
            d1 = fmaf(acc[m][n][2], cd[n * 2], fmaf(acc[m][n][3], cd[n * 2 + 1], d1));
        }
#pragma unroll
        for (int o = 1; o <= 2; o <<= 1) {
            s0 += __shfl_xor_sync(FULLM, s0, o);
            s1 += __shfl_xor_sync(FULLM, s1, o);
            d0 += __shfl_xor_sync(FULLM, d0, o);
            d1 += __shfl_xor_sync(FULLM, d1, o);
        }
        if (t == 0) {
            if (row0 < M) { g_as1[row0 * H1 + wn] = s0; g_ad1[row0 * H1 + wn] = d0; }
            if (row1 < M) { g_as1[row1 * H1 + wn] = s1; g_ad1[row1 * H1 + wn] = d1; }
        }
    }
}

// ---------------- fused attn1 + ELU + gemm2 + layer-2 logits -----------------
__global__ void __launch_bounds__(256)
k_attn1f(const float* __restrict__ b1, const float* __restrict__ W2,
         const float* __restrict__ a_s2, const float* __restrict__ a_d2, int N) {
    __shared__ float w2s[HC1 * C2];
    __shared__ float hs[8][HC1 + 4];
    __shared__ int   s_src[8][32];
    __shared__ float s_w[8][32][4];

    const int tid = threadIdx.x;
    const int wid = tid >> 5, lane = tid & 31;
#pragma unroll
    for (int i = tid; i < HC1 * C2; i += 256) w2s[i] = W2[i];
    __syncthreads();

    const int node = blockIdx.x * 8 + wid;
    if (node < N) {
        const int beg = g_rowptr[node], end = g_rowptr[node + 1];
        const float4 ad4 = *reinterpret_cast<const float4*>(&g_ad1[node * H1]);
        const int half = lane >> 4;
        const int hc   = lane & 15;
        const int headp = hc >> 2;

        float acc8[8];
#pragma unroll
        for (int i = 0; i < 8; i++) acc8[i] = 0.f;
        float4 ssum = make_float4(0.f, 0.f, 0.f, 0.f);

        for (int base = beg; base < end; base += 32) {
            int i = base + lane;
            int src_l = 0;
            float4 w4 = make_float4(0.f, 0.f, 0.f, 0.f);
            if (i < end) {
                src_l = g_csr[i];
                float4 as4 = *reinterpret_cast<const float4*>(&g_as1[src_l * H1]);
                w4.x = __expf(lrelu(as4.x + ad4.x));
                w4.y = __expf(lrelu(as4.y + ad4.y));
                w4.z = __expf(lrelu(as4.z + ad4.z));
                w4.w = __expf(lrelu(as4.w + ad4.w));
            }
            ssum.x += w4.x; ssum.y += w4.y; ssum.z += w4.z; ssum.w += w4.w;
            s_src[wid][lane] = src_l;
            *reinterpret_cast<float4*>(&s_w[wid][lane][0]) = w4;
            __syncwarp();

            int cnt = min(32, end - base);
            for (int j = 0; j < cnt; j += 8) {
                int p[4]; float wg[4];
#pragma unroll
                for (int q = 0; q < 4; q++) {
                    int e = j + q * 2 + half;
                    p[q]  = s_src[wid][e];
                    wg[q] = s_w[wid][e][headp];
                }
                uint4 v[4];
#pragma unroll
                for (int q = 0; q < 4; q++)
                    v[q] = *reinterpret_cast<const uint4*>(&g_h1[(long)p[q] * HC1 + hc * 8]);
#pragma unroll
                for (int q = 0; q < 4; q++) {
                    float2 f0 = __half22float2(*reinterpret_cast<__half2*>(&v[q].x));
                    float2 f1 = __half22float2(*reinterpret_cast<__half2*>(&v[q].y));
                    float2 f2 = __half22float2(*reinterpret_cast<__half2*>(&v[q].z));
                    float2 f3 = __half22float2(*reinterpret_cast<__half2*>(&v[q].w));
                    acc8[0] = fmaf(f0.x, wg[q], acc8[0]);
                    acc8[1] = fmaf(f0.y, wg[q], acc8[1]);
                    acc8[2] = fmaf(f1.x, wg[q], acc8[2]);
                    acc8[3] = fmaf(f1.y, wg[q], acc8[3]);
                    acc8[4] = fmaf(f2.x, wg[q], acc8[4]);
                    acc8[5] = fmaf(f2.y, wg[q], acc8[5]);
                    acc8[6] = fmaf(f3.x, wg[q], acc8[6]);
                    acc8[7] = fmaf(f3.y, wg[q], acc8[7]);
                }
            }
            __syncwarp();
        }
#pragma unroll
        for (int i = 0; i < 8; i++) acc8[i] += __shfl_xor_sync(FULLM, acc8[i], 16);
#pragma unroll
        for (int o = 16; o; o >>= 1) {
            ssum.x += __shfl_xor_sync(FULLM, ssum.x, o);
            ssum.y += __shfl_xor_sync(FULLM, ssum.y, o);
            ssum.z += __shfl_xor_sync(FULLM, ssum.z, o);
            ssum.w += __shfl_xor_sync(FULLM, ssum.w, o);
        }
        if (lane < 16) {
            float sh = (headp < 2) ? (headp == 0 ? ssum.x : ssum.y)
                                   : (headp == 2 ? ssum.z : ssum.w);
            float inv = 1.f / (sh + EPSV);
            float4 bb0 = *reinterpret_cast<const float4*>(&b1[hc * 8]);
            float4 bb1 = *reinterpret_cast<const float4*>(&b1[hc * 8 + 4]);
            float o8[8];
            o8[0] = fmaf(acc8[0], inv, bb0.x);
            o8[1] = fmaf(acc8[1], inv, bb0.y);
            o8[2] = fmaf(acc8[2], inv, bb0.z);
            o8[3] = fmaf(acc8[3], inv, bb0.w);
            o8[4] = fmaf(acc8[4], inv, bb1.x);
            o8[5] = fmaf(acc8[5], inv, bb1.y);
            o8[6] = fmaf(acc8[6], inv, bb1.z);
            o8[7] = fmaf(acc8[7], inv, bb1.w);
#pragma unroll
            for (int i = 0; i < 8; i++)
                o8[i] = o8[i] > 0.f ? o8[i] : (__expf(o8[i]) - 1.f);
            *reinterpret_cast<float4*>(&hs[wid][hc * 8])     = *reinterpret_cast<float4*>(&o8[0]);
            *reinterpret_cast<float4*>(&hs[wid][hc * 8 + 4]) = *reinterpret_cast<float4*>(&o8[4]);
        }
    }
    __syncwarp();

    if (node < N) {
        const int c = lane & 15, sub = lane >> 4;
        float acc2 = 0.f;
#pragma unroll
        for (int kk = 0; kk < 16; kk++) {
            int k = sub * 64 + kk * 4;
            float4 hv = *reinterpret_cast<const float4*>(&hs[wid][k]);
            acc2 = fmaf(hv.x, w2s[(k + 0) * C2 + c], acc2);
            acc2 = fmaf(hv.y, w2s[(k + 1) * C2 + c], acc2);
            acc2 = fmaf(hv.z, w2s[(k + 2) * C2 + c], acc2);
            acc2 = fmaf(hv.w, w2s[(k + 3) * C2 + c], acc2);
        }
        acc2 += __shfl_xor_sync(FULLM, acc2, 16);

        float s = acc2 * __ldg(&a_s2[c]);
        float d = acc2 * __ldg(&a_d2[c]);
#pragma unroll
        for (int o = 8; o; o >>= 1) {
            s += __shfl_xor_sync(FULLM, s, o);
            d += __shfl_xor_sync(FULLM, d, o);
        }
        if (lane < 16) {
            g_h2[node * C2 + c] = __float2half_rn(acc2);
            if (c == 0) { g_as2[node] = s; g_ad2[node] = d; }
        }
    }
}

// ---------------- attention + aggregate, layer 2 (fp16 h2) -------------------
__global__ void __launch_bounds__(256)
k_attn2(const float* __restrict__ b2, float* __restrict__ out, int N) {
    __shared__ int   s_src[8][32];
    __shared__ float s_w[8][32];

    int tid = threadIdx.x;
    int wid = tid >> 5, lane = tid & 31;
    int w = blockIdx.x * 8 + wid;
    if (w >= N) return;
    int beg = g_rowptr[w], end = g_rowptr[w + 1];
    float adv = g_ad2[w];
    int cc = lane & 15;
    int half = (lane >> 4) * 16;

    float acc = 0.f, ssum = 0.f;
    for (int base = beg; base < end; base += 32) {
        int i = base + lane;
        int src_l = 0; float wt_l = 0.f;
        if (i < end) {
            src_l = g_csr[i];
            wt_l = __expf(lrelu(g_as2[src_l] + adv));
        }
        ssum += wt_l;
        s_src[wid][lane] = src_l;
        s_w[wid][lane] = wt_l;
        __syncwarp();
#pragma unroll
        for (int jj = 0; jj < 16; jj += 8) {
            int p[8]; float wg[8];
#pragma unroll
            for (int q = 0; q < 8; q++) {
                p[q]  = s_src[wid][half + jj + q];
                wg[q] = s_w[wid][half + jj + q];
            }
            float vv[8];
#pragma unroll
            for (int q = 0; q < 8; q++) vv[q] = __half2float(g_h2[p[q] * C2 + cc]);
#pragma unroll
            for (int q = 0; q < 8; q++) acc = fmaf(vv[q], wg[q], acc);
        }
        __syncwarp();
    }
    acc += __shfl_xor_sync(FULLM, acc, 16);
#pragma unroll
    for (int o = 16; o; o >>= 1) ssum += __shfl_xor_sync(FULLM, ssum, o);
    if (lane < 16) out[w * C2 + lane] = acc / (ssum + EPSV) + b2[lane];
}

// ---------------- launch -----------------------------------------------------
extern "C" void kernel_launch(void* const* d_in, const int* in_sizes, int n_in,
                              void* d_out, int out_size) {
    const float* x    = (const float*)d_in[0];
    const int*   ei   = (const int*)d_in[1];
    const float* W1   = (const float*)d_in[2];
    const float* a_s1 = (const float*)d_in[3];
    const float* a_d1 = (const float*)d_in[4];
    const float* b1   = (const float*)d_in[5];
    const float* W2   = (const float*)d_in[6];
    const float* a_s2 = (const float*)d_in[7];
    const float* a_d2 = (const float*)d_in[8];
    const float* b2   = (const float*)d_in[9];
    float* out = (float*)d_out;

    const int Fin = in_sizes[2] / in_sizes[5];   // 256
    const int N   = in_sizes[0] / Fin;           // 50000
    const int E   = in_sizes[1] / 2;             // 800000
    const int P   = (N + 255) / 256;

    static cudaStream_t s2 = nullptr;
    static cudaEvent_t  evA = nullptr, evB = nullptr;
    if (s2 == nullptr) {
        cudaStreamCreateWithFlags(&s2, cudaStreamNonBlocking);
        cudaEventCreateWithFlags(&evA, cudaEventDisableTiming);
        cudaEventCreateWithFlags(&evB, cudaEventDisableTiming);
    }

    // fork: CSR build on s2, GEMM1 on main stream
    cudaEventRecord(evA, 0);
    cudaStreamWaitEvent(s2, evA, 0);

    k_gemm1_tc<<<(N + 63) / 64, 256>>>(x, W1, a_s1, a_d1, N);

    k_zero<<<(N + 255) / 256, 256, 0, s2>>>(N);
    k_histp<<<(E / 4 + 256) / 256, 256, 0, s2>>>(ei + E, E);
    k_scan1<<<P, 256, 0, s2>>>(N);
    k_scan2<<<1, 256, 0, s2>>>(P, N);
    k_scan3<<<P, 256, 0, s2>>>(N);
    k_scatter2<<<(E / 4 + 256) / 256, 256, 0, s2>>>(ei, ei + E, E);

    // join
    cudaEventRecord(evB, s2);
    cudaStreamWaitEvent(0, evB, 0);

    // fused layer-1 aggregate + ELU + gemm2 + layer-2 logits
    k_attn1f<<<(N + 7) / 8, 256>>>(b1, W2, a_s2, a_d2, N);

    // layer-2 aggregate
    k_attn2<<<(N + 7) / 8, 256>>>(b2, out, N);
}